// round 15
// baseline (speedup 1.0000x reference)
#include <cuda_runtime.h>
#include <cuda_bf16.h>
#include <cstdint>

#define DM   1024
#define BATCH 4
#define SEQ  2048
#define NH   16
#define HD   64
#define MTOT (BATCH*SEQ)   /* 8192 */
#define EPS  1e-5f

typedef __nv_bfloat16 bf16;

// ---------------- scratch (device globals; no allocations allowed) ----------
__device__ float g_qn[MTOT*DM];
__device__ float g_kn[MTOT*DM];
__device__ float g_vn[MTOT*DM];
__device__ bf16  g_wh[4][DM*DM], g_wl[4][DM*DM];   /* pre-split weights [K][N] */
__device__ bf16  g_qph[MTOT*DM], g_qpl[MTOT*DM];   /* pre-split projections   */
__device__ bf16  g_kph[MTOT*DM], g_kpl[MTOT*DM];
__device__ bf16  g_vph[MTOT*DM], g_vpl[MTOT*DM];
__device__ float g_ao[MTOT*DM];
__device__ float g_y [MTOT*DM];
__device__ float g_gate[MTOT];

// ---------------- bf16 mma m16n8k16 + ldmatrix helpers ----------------------
__device__ __forceinline__ void mma_bf16(float c[4], const uint32_t a[4], const uint32_t b[2]) {
    asm volatile(
        "mma.sync.aligned.m16n8k16.row.col.f32.bf16.bf16.f32 "
        "{%0,%1,%2,%3}, {%4,%5,%6,%7}, {%8,%9}, {%0,%1,%2,%3};\n"
        : "+f"(c[0]), "+f"(c[1]), "+f"(c[2]), "+f"(c[3])
        : "r"(a[0]), "r"(a[1]), "r"(a[2]), "r"(a[3]), "r"(b[0]), "r"(b[1]));
}
__device__ __forceinline__ uint32_t smem_u32(const void* p) {
    return (uint32_t)__cvta_generic_to_shared(p);
}
__device__ __forceinline__ void ldmx4(uint32_t r[4], uint32_t addr) {
    asm volatile("ldmatrix.sync.aligned.m8n8.x4.shared.b16 {%0,%1,%2,%3}, [%4];"
                 : "=r"(r[0]), "=r"(r[1]), "=r"(r[2]), "=r"(r[3]) : "r"(addr));
}
__device__ __forceinline__ void ldmx4t(uint32_t r[4], uint32_t addr) {
    asm volatile("ldmatrix.sync.aligned.m8n8.x4.trans.shared.b16 {%0,%1,%2,%3}, [%4];"
                 : "=r"(r[0]), "=r"(r[1]), "=r"(r[2]), "=r"(r[3]) : "r"(addr));
}
__device__ __forceinline__ uint32_t packb(float e0, float e1) {
    uint32_t r;
    asm("cvt.rn.bf16x2.f32 %0, %1, %2;" : "=r"(r) : "f"(e1), "f"(e0));
    return r;
}
__device__ __forceinline__ float hi_bf16(float x) {
    return __bfloat162float(__float2bfloat16(x));
}
__device__ __forceinline__ void split4b(float4 v, uint2& h, uint2& l) {
    float hx = hi_bf16(v.x), hy = hi_bf16(v.y), hz = hi_bf16(v.z), hw = hi_bf16(v.w);
    h.x = packb(hx, hy); h.y = packb(hz, hw);
    l.x = packb(v.x - hx, v.y - hy); l.y = packb(v.z - hz, v.w - hw);
}

// ---------------- weight split: f32 -> bf16 hi/lo (layout preserved [K][N]) --
__global__ __launch_bounds__(256) void splitw_kernel(
    const float* __restrict__ W0, const float* __restrict__ W1,
    const float* __restrict__ W2, const float* __restrict__ W3,
    bf16* __restrict__ H0, bf16* __restrict__ L0,
    bf16* __restrict__ H1, bf16* __restrict__ L1,
    bf16* __restrict__ H2, bf16* __restrict__ L2,
    bf16* __restrict__ H3, bf16* __restrict__ L3)
{
    const float* W[4] = {W0, W1, W2, W3};
    bf16* H[4] = {H0, H1, H2, H3};
    bf16* L[4] = {L0, L1, L2, L3};
    int m = blockIdx.y;
    int i = blockIdx.x * 256 + threadIdx.x;          // float4 index
    float4 v = ((const float4*)W[m])[i];
    uint2 h, l; split4b(v, h, l);
    *(uint2*)&H[m][(size_t)i*4] = h;
    *(uint2*)&L[m][(size_t)i*4] = l;
}

// ---------------- fused pre-LN for q/k/v + gate (fp32 out) -------------------
__global__ __launch_bounds__(256) void ln3_kernel(
    const float* __restrict__ q, const float* __restrict__ k, const float* __restrict__ v,
    const float* __restrict__ gq, const float* __restrict__ bq,
    const float* __restrict__ gkv, const float* __restrict__ bkv,
    const float* __restrict__ Wg,
    float* __restrict__ oq, float* __restrict__ ok, float* __restrict__ ov,
    float* __restrict__ gate)
{
    const int row = blockIdx.x, src = blockIdx.y;
    const float* x  = src == 0 ? q  : (src == 1 ? k  : v);
    float*       out= src == 0 ? oq : (src == 1 ? ok : ov);
    const float* gg = src == 0 ? gq : gkv;
    const float* bb = src == 0 ? bq : bkv;
    const int tid = threadIdx.x, lane = tid & 31, warp = tid >> 5;

    float4 xv = ((const float4*)(x + (size_t)row*DM))[tid];
    float s  = xv.x + xv.y + xv.z + xv.w;
    float ss = xv.x*xv.x + xv.y*xv.y + xv.z*xv.z + xv.w*xv.w;

    __shared__ __align__(16) float red[16];
    #pragma unroll
    for (int off = 16; off; off >>= 1) {
        s  += __shfl_xor_sync(0xffffffffu, s,  off);
        ss += __shfl_xor_sync(0xffffffffu, ss, off);
    }
    if (lane == 0) { red[warp] = s; red[8 + warp] = ss; }
    __syncthreads();
    float st = 0.f, sst = 0.f;
    #pragma unroll
    for (int i = 0; i < 8; i++) { st += red[i]; sst += red[8 + i]; }
    float mu   = st * (1.f/DM);
    float var  = sst * (1.f/DM) - mu*mu;
    float rstd = rsqrtf(var + EPS);

    float4 gv = ((const float4*)gg)[tid];
    float4 bv = ((const float4*)bb)[tid];
    float4 yv;
    yv.x = (xv.x - mu)*rstd*gv.x + bv.x;
    yv.y = (xv.y - mu)*rstd*gv.y + bv.y;
    yv.z = (xv.z - mu)*rstd*gv.z + bv.z;
    yv.w = (xv.w - mu)*rstd*gv.w + bv.w;
    ((float4*)(out + (size_t)row*DM))[tid] = yv;

    if (src == 0) {  // gate = sigmoid(qn . Wg)
        float4 wv = ((const float4*)Wg)[tid];
        float gp = yv.x*wv.x + yv.y*wv.y + yv.z*wv.z + yv.w*wv.w;
        #pragma unroll
        for (int off = 16; off; off >>= 1) gp += __shfl_xor_sync(0xffffffffu, gp, off);
        __syncthreads();
        if (lane == 0) red[warp] = gp;
        __syncthreads();
        if (tid == 0) {
            float t = 0.f;
            #pragma unroll
            for (int i = 0; i < 8; i++) t += red[i];
            gate[row] = 1.f / (1.f + __expf(-t));
        }
    }
}

// ---------------- 3xBF16 GEMM, double-buffered; dual epilogue ----------------
// BM=128, BN=64, BK=32. 256 threads, 8 warps (4m x 2n), warp tile 32x32.
#define AST 40
#define BST 72
#define GBUF (128*AST*2 + 32*BST*2)   /* elems per buffer = 14848 (29,696 B) */
#define GEMM_SMEM (2*GBUF*2)          /* bytes = 59,392 */
__global__ __launch_bounds__(256, 2) void gemm_bf16x3(
    const float* __restrict__ A0, const float* __restrict__ A1, const float* __restrict__ A2,
    const bf16* __restrict__ Wh_base, const bf16* __restrict__ Wl_base, int woff,
    const float* __restrict__ b0, const float* __restrict__ b1, const float* __restrict__ b2,
    const float* __restrict__ gate, float* __restrict__ Cf,
    bf16* __restrict__ Ch0, bf16* __restrict__ Cl0,
    bf16* __restrict__ Ch1, bf16* __restrict__ Cl1,
    bf16* __restrict__ Ch2, bf16* __restrict__ Cl2)
{
    extern __shared__ __align__(16) bf16 gsm[];

    const int z = blockIdx.z;
    const float* A    = z == 0 ? A0 : (z == 1 ? A1 : A2);
    const float* bias = z == 0 ? b0 : (z == 1 ? b1 : b2);
    bf16* Ch = z == 0 ? Ch0 : (z == 1 ? Ch1 : Ch2);
    bf16* Cl = z == 0 ? Cl0 : (z == 1 ? Cl1 : Cl2);
    const bf16* Wh_g = Wh_base + (size_t)(woff + z)*DM*DM;
    const bf16* Wl_g = Wl_base + (size_t)(woff + z)*DM*DM;

    const int tid = threadIdx.x, lane = tid & 31, warp = tid >> 5;
    const int bm = blockIdx.y * 128, bn = blockIdx.x * 64;
    const int wm = (warp >> 1) * 32, wn = (warp & 1) * 32;

    float acc[2][4][4] = {};
    float4 pa[4];
    uint4 pb_h, pb_l;

    const int br = tid >> 3, bc = (tid & 7) * 8;

    auto loadT = [&](int k0) {
        #pragma unroll
        for (int i = 0; i < 4; i++) {
            int idx = (tid + i*256) * 4;
            int m = idx >> 5, kk = idx & 31;
            pa[i] = *(const float4*)(A + (size_t)(bm + m)*1024 + k0 + kk);
        }
        pb_h = *(const uint4*)(Wh_g + (size_t)(k0 + br)*DM + bn + bc);
        pb_l = *(const uint4*)(Wl_g + (size_t)(k0 + br)*DM + bn + bc);
    };
    auto storeT = [&](int buf) {
        bf16* Ah = gsm + buf*GBUF;
        bf16* Al = Ah + 128*AST;
        bf16* Bh = Al + 128*AST;
        bf16* Bl = Bh + 32*BST;
        #pragma unroll
        for (int i = 0; i < 4; i++) {
            int idx = (tid + i*256) * 4;
            int m = idx >> 5, kk = idx & 31;
            uint2 h, l; split4b(pa[i], h, l);
            *(uint2*)&Ah[m*AST + kk] = h;
            *(uint2*)&Al[m*AST + kk] = l;
        }
        *(uint4*)&Bh[br*BST + bc] = pb_h;
        *(uint4*)&Bl[br*BST + bc] = pb_l;
    };

    loadT(0); storeT(0); __syncthreads();

    for (int t = 0; t < 32; t++) {
        const int cur = t & 1;
        if (t + 1 < 32) loadT((t + 1) * 32);

        const uint32_t base = smem_u32(gsm + cur*GBUF);
        const uint32_t ah_b = base;
        const uint32_t al_b = base + 128*AST*2;
        const uint32_t bh_b = base + 128*AST*4;
        const uint32_t bl_b = bh_b + 32*BST*2;

        #pragma unroll
        for (int kc = 0; kc < 2; kc++) {
            uint32_t af_h[2][4], af_l[2][4];
            #pragma unroll
            for (int mi = 0; mi < 2; mi++) {
                uint32_t off = ((wm + mi*16 + (lane & 15))*AST + kc*16 + (lane >> 4)*8) * 2;
                ldmx4(af_h[mi], ah_b + off);
                ldmx4(af_l[mi], al_b + off);
            }
            uint32_t bf_h[2][4], bf_l[2][4];
            #pragma unroll
            for (int nip = 0; nip < 2; nip++) {
                uint32_t off = ((kc*16 + (lane & 15))*BST + wn + nip*16 + (lane >> 4)*8) * 2;
                ldmx4t(bf_h[nip], bh_b + off);
                ldmx4t(bf_l[nip], bl_b + off);
            }
            #pragma unroll
            for (int mi = 0; mi < 2; mi++)
                #pragma unroll
                for (int ni = 0; ni < 4; ni++) {
                    const uint32_t* b2h = &bf_h[ni >> 1][(ni & 1)*2];
                    const uint32_t* b2l = &bf_l[ni >> 1][(ni & 1)*2];
                    mma_bf16(acc[mi][ni], af_h[mi], b2h);
                    mma_bf16(acc[mi][ni], af_l[mi], b2h);
                    mma_bf16(acc[mi][ni], af_h[mi], b2l);
                }
        }

        if (t + 1 < 32) {
            storeT(1 - cur);
            __syncthreads();
        }
    }

    #pragma unroll
    for (int mi = 0; mi < 2; mi++) {
        #pragma unroll
        for (int ni = 0; ni < 4; ni++) {
            int r0 = bm + wm + mi*16 + (lane >> 2);
            int c0 = bn + wn + ni*8 + 2*(lane & 3);
            float bz0 = bias[c0], bz1 = bias[c0 + 1];
            float v0 = acc[mi][ni][0] + bz0;
            float v1 = acc[mi][ni][1] + bz1;
            float v2 = acc[mi][ni][2] + bz0;
            float v3 = acc[mi][ni][3] + bz1;
            if (Cf) {
                float gA = gate[r0], gB = gate[r0 + 8];
                Cf[(size_t)r0*DM + c0]         = v0*gA;
                Cf[(size_t)r0*DM + c0 + 1]     = v1*gA;
                Cf[(size_t)(r0+8)*DM + c0]     = v2*gB;
                Cf[(size_t)(r0+8)*DM + c0 + 1] = v3*gB;
            } else {
                float h0 = hi_bf16(v0), h1 = hi_bf16(v1);
                float h2 = hi_bf16(v2), h3 = hi_bf16(v3);
                *(uint32_t*)&Ch[(size_t)r0*DM + c0]     = packb(h0, h1);
                *(uint32_t*)&Ch[(size_t)(r0+8)*DM + c0] = packb(h2, h3);
                *(uint32_t*)&Cl[(size_t)r0*DM + c0]     = packb(v0 - h0, v1 - h1);
                *(uint32_t*)&Cl[(size_t)(r0+8)*DM + c0] = packb(v2 - h2, v3 - h3);
            }
        }
    }
}

// ---------------- flash attention: 256 q-rows/CTA, 32 rows/warp, pre-split ---
#define KST 72
#define KVBUF (4*64*KST)       /* elems per buffer = 18432 (36,864 B) */
#define ATTN_SMEM (2*KVBUF*2)  /* bytes = 73,728 (Q staging aliases both bufs) */
#define LOG2E 1.44269504088896f
__global__ __launch_bounds__(256, 1) void attn_bf16(
    const bf16* __restrict__ Qh_g, const bf16* __restrict__ Ql_g,
    const bf16* __restrict__ Kh_g, const bf16* __restrict__ Kl_g,
    const bf16* __restrict__ Vh_g, const bf16* __restrict__ Vl_g,
    float* __restrict__ O)
{
    extern __shared__ __align__(16) bf16 asm_[];
    bf16* Qh = asm_;                 // 256*KST (aliases both KV buffers)
    bf16* Ql = asm_ + 256*KST;

    const int tid = threadIdx.x, lane = tid & 31, warp = tid >> 5;
    const int qt = blockIdx.x, h = blockIdx.y, b = blockIdx.z;
    const size_t qrow0 = (size_t)(b*SEQ + qt*256);
    const size_t kvrow0 = (size_t)(b*SEQ);
    const int hc = h * HD;

    // stage pre-split Q tile 256x64 (pure copy)
    #pragma unroll
    for (int i = 0; i < 8; i++) {
        int idx = tid + i*256;
        int r = idx >> 3, c8 = (idx & 7) * 8;
        *(uint4*)&Qh[r*KST + c8] = *(const uint4*)(Qh_g + (qrow0 + r)*DM + hc + c8);
        *(uint4*)&Ql[r*KST + c8] = *(const uint4*)(Ql_g + (qrow0 + r)*DM + hc + c8);
    }
    __syncthreads();

    uint32_t qh[2][4][4], ql[2][4][4];
    {
        const uint32_t qh_b = smem_u32(Qh), ql_b = smem_u32(Ql);
        #pragma unroll
        for (int mi = 0; mi < 2; mi++)
            #pragma unroll
            for (int kc = 0; kc < 4; kc++) {
                uint32_t off = ((warp*32 + mi*16 + (lane & 15))*KST + kc*16 + (lane >> 4)*8) * 2;
                ldmx4(qh[mi][kc], qh_b + off);
                ldmx4(ql[mi][kc], ql_b + off);
            }
    }
    __syncthreads();   // Q frags in regs; buffers may now be overwritten

    float o[2][8][4] = {};
    float mrow[2][2] = {{-1e30f,-1e30f},{-1e30f,-1e30f}};
    float lrow[2][2] = {{0.f,0.f},{0.f,0.f}};

    uint4 pkh[2], pkl[2], pvh[2], pvl[2];
    auto loadKV = [&](int t) {
        #pragma unroll
        for (int i = 0; i < 2; i++) {
            int idx = tid + i*256;
            int r = idx >> 3, c8 = (idx & 7) * 8;
            const size_t g = (kvrow0 + t*64 + r)*DM + hc + c8;
            pkh[i] = *(const uint4*)(Kh_g + g);
            pkl[i] = *(const uint4*)(Kl_g + g);
            pvh[i] = *(const uint4*)(Vh_g + g);
            pvl[i] = *(const uint4*)(Vl_g + g);
        }
    };
    auto storeKV = [&](int buf) {
        bf16* Kh = asm_ + buf*KVBUF;
        bf16* Kl = Kh + 64*KST;
        bf16* Vh = Kl + 64*KST;
        bf16* Vl = Vh + 64*KST;
        #pragma unroll
        for (int i = 0; i < 2; i++) {
            int idx = tid + i*256;
            int r = idx >> 3, c8 = (idx & 7) * 8;
            *(uint4*)&Kh[r*KST + c8] = pkh[i];
            *(uint4*)&Kl[r*KST + c8] = pkl[i];
            *(uint4*)&Vh[r*KST + c8] = pvh[i];
            *(uint4*)&Vl[r*KST + c8] = pvl[i];
        }
    };

    loadKV(0); storeKV(0); __syncthreads();

    for (int t = 0; t < SEQ/64; t++) {
        const int cur = t & 1;
        if (t + 1 < SEQ/64) loadKV(t + 1);

        const uint32_t base = smem_u32(asm_ + cur*KVBUF);
        const uint32_t kh_b = base;
        const uint32_t kl_b = base + 64*KST*2;
        const uint32_t vh_b = base + 64*KST*4;
        const uint32_t vl_b = base + 64*KST*6;

        // ---- S = Q K^T (3xBF16), K-frags amortized over 2 m-frags ----
        float s[2][8][4] = {};
        #pragma unroll
        for (int kc = 0; kc < 4; kc++) {
            #pragma unroll
            for (int nip = 0; nip < 4; nip++) {
                uint32_t off = ((nip*16 + (lane >> 4)*8 + (lane & 7))*KST
                                + kc*16 + ((lane >> 3) & 1)*8) * 2;
                uint32_t kf_h[4], kf_l[4];
                ldmx4(kf_h, kh_b + off);
                ldmx4(kf_l, kl_b + off);
                #pragma unroll
                for (int mi = 0; mi < 2; mi++)
                    #pragma unroll
                    for (int hf = 0; hf < 2; hf++) {
                        int ni = nip*2 + hf;
                        mma_bf16(s[mi][ni], qh[mi][kc], &kf_h[hf*2]);
                        mma_bf16(s[mi][ni], ql[mi][kc], &kf_h[hf*2]);
                        mma_bf16(s[mi][ni], qh[mi][kc], &kf_l[hf*2]);
                    }
            }
        }
        #pragma unroll
        for (int mi = 0; mi < 2; mi++)
            #pragma unroll
            for (int ni = 0; ni < 8; ni++) {
                s[mi][ni][0] *= 0.125f*LOG2E; s[mi][ni][1] *= 0.125f*LOG2E;
                s[mi][ni][2] *= 0.125f*LOG2E; s[mi][ni][3] *= 0.125f*LOG2E;
            }

        // ---- online softmax per (m-frag, row-half), base-2 domain ----
        #pragma unroll
        for (int mi = 0; mi < 2; mi++)
            #pragma unroll
            for (int rh = 0; rh < 2; rh++) {
                float mx = -1e30f;
                #pragma unroll
                for (int ni = 0; ni < 8; ni++)
                    mx = fmaxf(mx, fmaxf(s[mi][ni][rh*2], s[mi][ni][rh*2+1]));
                mx = fmaxf(mx, __shfl_xor_sync(0xffffffffu, mx, 1));
                mx = fmaxf(mx, __shfl_xor_sync(0xffffffffu, mx, 2));
                float mnew  = fmaxf(mrow[mi][rh], mx);
                float alpha = exp2f(mrow[mi][rh] - mnew);
                mrow[mi][rh] = mnew;
                float sum = 0.f;
                #pragma unroll
                for (int ni = 0; ni < 8; ni++) {
                    s[mi][ni][rh*2]   = exp2f(s[mi][ni][rh*2]   - mnew);
                    s[mi][ni][rh*2+1] = exp2f(s[mi][ni][rh*2+1] - mnew);
                    sum += s[mi][ni][rh*2] + s[mi][ni][rh*2+1];
                }
                sum += __shfl_xor_sync(0xffffffffu, sum, 1);
                sum += __shfl_xor_sync(0xffffffffu, sum, 2);
                lrow[mi][rh] = lrow[mi][rh]*alpha + sum;
                #pragma unroll
                for (int ni = 0; ni < 8; ni++) {
                    o[mi][ni][rh*2] *= alpha; o[mi][ni][rh*2+1] *= alpha;
                }
            }

        // ---- O += P V (3xBF16); V-frags amortized over 2 m-frags ----
        #pragma unroll
        for (int kcp = 0; kcp < 4; kcp++) {
            uint32_t pa_h[2][4], pa_l[2][4];
            #pragma unroll
            for (int mi = 0; mi < 2; mi++)
                #pragma unroll
                for (int j = 0; j < 2; j++) {
                    float e0 = s[mi][2*kcp + j][0], e1 = s[mi][2*kcp + j][1];
                    float e2 = s[mi][2*kcp + j][2], e3 = s[mi][2*kcp + j][3];
                    float h0 = hi_bf16(e0), h1 = hi_bf16(e1), h2 = hi_bf16(e2), h3 = hi_bf16(e3);
                    pa_h[mi][2*j]   = packb(h0, h1);
                    pa_h[mi][2*j+1] = packb(h2, h3);
                    pa_l[mi][2*j]   = packb(e0 - h0, e1 - h1);
                    pa_l[mi][2*j+1] = packb(e2 - h2, e3 - h3);
                }
            #pragma unroll
            for (int nip = 0; nip < 4; nip++) {
                uint32_t off = ((kcp*16 + ((lane >> 3) & 1)*8 + (lane & 7))*KST
                                + nip*16 + (lane >> 4)*8) * 2;
                uint32_t vf_h[4], vf_l[4];
                ldmx4t(vf_h, vh_b + off);
                ldmx4t(vf_l, vl_b + off);
                #pragma unroll
                for (int mi = 0; mi < 2; mi++)
                    #pragma unroll
                    for (int hf = 0; hf < 2; hf++) {
                        int ni = nip*2 + hf;
                        mma_bf16(o[mi][ni], pa_h[mi], &vf_h[hf*2]);
                        mma_bf16(o[mi][ni], pa_l[mi], &vf_h[hf*2]);
                        mma_bf16(o[mi][ni], pa_h[mi], &vf_l[hf*2]);
                    }
            }
        }

        if (t + 1 < SEQ/64) {
            storeKV(1 - cur);
            __syncthreads();
        }
    }

    #pragma unroll
    for (int mi = 0; mi < 2; mi++) {
        float inv0 = 1.f / lrow[mi][0], inv1 = 1.f / lrow[mi][1];
        int r = warp*32 + mi*16 + (lane >> 2);
        float* obase = O + (qrow0*DM + hc);
        #pragma unroll
        for (int ni = 0; ni < 8; ni++) {
            int c = ni*8 + 2*(lane & 3);
            obase[(size_t)r*DM + c]         = o[mi][ni][0]*inv0;
            obase[(size_t)r*DM + c + 1]     = o[mi][ni][1]*inv0;
            obase[(size_t)(r+8)*DM + c]     = o[mi][ni][2]*inv1;
            obase[(size_t)(r+8)*DM + c + 1] = o[mi][ni][3]*inv1;
        }
    }
}

// ---------------- final LN ---------------------------------------------------
__global__ __launch_bounds__(256) void ln_out_kernel(
    const float* __restrict__ x, const float* __restrict__ gg,
    const float* __restrict__ bb, float* __restrict__ out)
{
    const int row = blockIdx.x;
    const int tid = threadIdx.x, lane = tid & 31, warp = tid >> 5;
    float4 xv = ((const float4*)(x + (size_t)row*DM))[tid];
    float s  = xv.x + xv.y + xv.z + xv.w;
    float ss = xv.x*xv.x + xv.y*xv.y + xv.z*xv.z + xv.w*xv.w;
    __shared__ __align__(16) float red[16];
    #pragma unroll
    for (int off = 16; off; off >>= 1) {
        s  += __shfl_xor_sync(0xffffffffu, s,  off);
        ss += __shfl_xor_sync(0xffffffffu, ss, off);
    }
    if (lane == 0) { red[warp] = s; red[8 + warp] = ss; }
    __syncthreads();
    float st = 0.f, sst = 0.f;
    #pragma unroll
    for (int i = 0; i < 8; i++) { st += red[i]; sst += red[8 + i]; }
    float mu   = st * (1.f/DM);
    float var  = sst * (1.f/DM) - mu*mu;
    float rstd = rsqrtf(var + EPS);
    float4 gv = ((const float4*)gg)[tid];
    float4 bv = ((const float4*)bb)[tid];
    float4 yv;
    yv.x = (xv.x - mu)*rstd*gv.x + bv.x;
    yv.y = (xv.y - mu)*rstd*gv.y + bv.y;
    yv.z = (xv.z - mu)*rstd*gv.z + bv.z;
    yv.w = (xv.w - mu)*rstd*gv.w + bv.w;
    ((float4*)(out + (size_t)row*DM))[tid] = yv;
}

// ---------------- launch -----------------------------------------------------
extern "C" void kernel_launch(void* const* d_in, const int* in_sizes, int n_in,
                              void* d_out, int out_size) {
    const float* query  = (const float*)d_in[0];
    const float* key_   = (const float*)d_in[1];
    const float* value  = (const float*)d_in[2];
    const float* Wq     = (const float*)d_in[3];
    const float* bq     = (const float*)d_in[4];
    const float* Wk     = (const float*)d_in[5];
    const float* bk     = (const float*)d_in[6];
    const float* Wv     = (const float*)d_in[7];
    const float* bv     = (const float*)d_in[8];
    const float* Wo     = (const float*)d_in[9];
    const float* bo     = (const float*)d_in[10];
    const float* Wg     = (const float*)d_in[11];
    const float* ln_q_g = (const float*)d_in[12];
    const float* ln_q_b = (const float*)d_in[13];
    const float* ln_kv_g= (const float*)d_in[14];
    const float* ln_kv_b= (const float*)d_in[15];
    const float* ln_o_g = (const float*)d_in[16];
    const float* ln_o_b = (const float*)d_in[17];

    float *qn, *kn, *vn, *ao, *y, *gate;
    bf16 *wh, *wl, *qph, *qpl, *kph, *kpl, *vph, *vpl;
    cudaGetSymbolAddress((void**)&qn,  g_qn);
    cudaGetSymbolAddress((void**)&kn,  g_kn);
    cudaGetSymbolAddress((void**)&vn,  g_vn);
    cudaGetSymbolAddress((void**)&ao,  g_ao);
    cudaGetSymbolAddress((void**)&y,   g_y);
    cudaGetSymbolAddress((void**)&gate,g_gate);
    cudaGetSymbolAddress((void**)&wh,  g_wh);
    cudaGetSymbolAddress((void**)&wl,  g_wl);
    cudaGetSymbolAddress((void**)&qph, g_qph); cudaGetSymbolAddress((void**)&qpl, g_qpl);
    cudaGetSymbolAddress((void**)&kph, g_kph); cudaGetSymbolAddress((void**)&kpl, g_kpl);
    cudaGetSymbolAddress((void**)&vph, g_vph); cudaGetSymbolAddress((void**)&vpl, g_vpl);

    bf16* whm[4] = {wh, wh + (size_t)DM*DM, wh + 2*(size_t)DM*DM, wh + 3*(size_t)DM*DM};
    bf16* wlm[4] = {wl, wl + (size_t)DM*DM, wl + 2*(size_t)DM*DM, wl + 3*(size_t)DM*DM};

    cudaFuncSetAttribute(gemm_bf16x3, cudaFuncAttributeMaxDynamicSharedMemorySize, GEMM_SMEM);
    cudaFuncSetAttribute(attn_bf16,  cudaFuncAttributeMaxDynamicSharedMemorySize, ATTN_SMEM);

    splitw_kernel<<<dim3(1024, 4), 256>>>(Wq, Wk, Wv, Wo,
        whm[0], wlm[0], whm[1], wlm[1], whm[2], wlm[2], whm[3], wlm[3]);
    ln3_kernel<<<dim3(MTOT, 3), 256>>>(query, key_, value,
                                       ln_q_g, ln_q_b, ln_kv_g, ln_kv_b,
                                       Wg, qn, kn, vn, gate);
    gemm_bf16x3<<<dim3(16, 64, 3), 256, GEMM_SMEM>>>(qn, kn, vn, wh, wl, 0,
                                          bq, bk, bv, nullptr, nullptr,
                                          qph, qpl, kph, kpl, vph, vpl);
    attn_bf16<<<dim3(SEQ/256, NH, BATCH), 256, ATTN_SMEM>>>(qph, qpl, kph, kpl, vph, vpl, ao);
    gemm_bf16x3<<<dim3(16, 64, 1), 256, GEMM_SMEM>>>(ao, ao, ao, wh, wl, 3,
                                          bo, bo, bo, gate, y,
                                          nullptr, nullptr, nullptr, nullptr, nullptr, nullptr);
    ln_out_kernel<<<MTOT, 256>>>(y, ln_o_g, ln_o_b, (float*)d_out);
}

// round 16
// speedup vs baseline: 1.0337x; 1.0337x over previous
#include <cuda_runtime.h>
#include <cuda_bf16.h>
#include <cstdint>

#define DM   1024
#define BATCH 4
#define SEQ  2048
#define NH   16
#define HD   64
#define MTOT (BATCH*SEQ)   /* 8192 */
#define EPS  1e-5f

typedef __nv_bfloat16 bf16;

// ---------------- scratch (device globals; no allocations allowed) ----------
__device__ bf16  g_qnh[MTOT*DM], g_qnl[MTOT*DM];   /* pre-split LN outputs    */
__device__ bf16  g_knh[MTOT*DM], g_knl[MTOT*DM];
__device__ bf16  g_vnh[MTOT*DM], g_vnl[MTOT*DM];
__device__ bf16  g_wh[4][DM*DM], g_wl[4][DM*DM];   /* pre-split weights [K][N] */
__device__ bf16  g_qph[MTOT*DM], g_qpl[MTOT*DM];   /* pre-split projections   */
__device__ bf16  g_kph[MTOT*DM], g_kpl[MTOT*DM];
__device__ bf16  g_vph[MTOT*DM], g_vpl[MTOT*DM];
__device__ bf16  g_aoh[MTOT*DM], g_aol[MTOT*DM];   /* pre-split attn output   */
__device__ float g_y [MTOT*DM];
__device__ float g_gate[MTOT];

// ---------------- bf16 mma m16n8k16 + ldmatrix helpers ----------------------
__device__ __forceinline__ void mma_bf16(float c[4], const uint32_t a[4], const uint32_t b[2]) {
    asm volatile(
        "mma.sync.aligned.m16n8k16.row.col.f32.bf16.bf16.f32 "
        "{%0,%1,%2,%3}, {%4,%5,%6,%7}, {%8,%9}, {%0,%1,%2,%3};\n"
        : "+f"(c[0]), "+f"(c[1]), "+f"(c[2]), "+f"(c[3])
        : "r"(a[0]), "r"(a[1]), "r"(a[2]), "r"(a[3]), "r"(b[0]), "r"(b[1]));
}
__device__ __forceinline__ uint32_t smem_u32(const void* p) {
    return (uint32_t)__cvta_generic_to_shared(p);
}
__device__ __forceinline__ void ldmx4(uint32_t r[4], uint32_t addr) {
    asm volatile("ldmatrix.sync.aligned.m8n8.x4.shared.b16 {%0,%1,%2,%3}, [%4];"
                 : "=r"(r[0]), "=r"(r[1]), "=r"(r[2]), "=r"(r[3]) : "r"(addr));
}
__device__ __forceinline__ void ldmx4t(uint32_t r[4], uint32_t addr) {
    asm volatile("ldmatrix.sync.aligned.m8n8.x4.trans.shared.b16 {%0,%1,%2,%3}, [%4];"
                 : "=r"(r[0]), "=r"(r[1]), "=r"(r[2]), "=r"(r[3]) : "r"(addr));
}
__device__ __forceinline__ uint32_t packb(float e0, float e1) {
    uint32_t r;
    asm("cvt.rn.bf16x2.f32 %0, %1, %2;" : "=r"(r) : "f"(e1), "f"(e0));
    return r;
}
__device__ __forceinline__ float hi_bf16(float x) {
    return __bfloat162float(__float2bfloat16(x));
}
__device__ __forceinline__ void split4b(float4 v, uint2& h, uint2& l) {
    float hx = hi_bf16(v.x), hy = hi_bf16(v.y), hz = hi_bf16(v.z), hw = hi_bf16(v.w);
    h.x = packb(hx, hy); h.y = packb(hz, hw);
    l.x = packb(v.x - hx, v.y - hy); l.y = packb(v.z - hz, v.w - hw);
}

// ---------------- weight split: f32 -> bf16 hi/lo (layout preserved [K][N]) --
__global__ __launch_bounds__(256) void splitw_kernel(
    const float* __restrict__ W0, const float* __restrict__ W1,
    const float* __restrict__ W2, const float* __restrict__ W3,
    bf16* __restrict__ H0, bf16* __restrict__ L0,
    bf16* __restrict__ H1, bf16* __restrict__ L1,
    bf16* __restrict__ H2, bf16* __restrict__ L2,
    bf16* __restrict__ H3, bf16* __restrict__ L3)
{
    const float* W[4] = {W0, W1, W2, W3};
    bf16* H[4] = {H0, H1, H2, H3};
    bf16* L[4] = {L0, L1, L2, L3};
    int m = blockIdx.y;
    int i = blockIdx.x * 256 + threadIdx.x;          // float4 index
    float4 v = ((const float4*)W[m])[i];
    uint2 h, l; split4b(v, h, l);
    *(uint2*)&H[m][(size_t)i*4] = h;
    *(uint2*)&L[m][(size_t)i*4] = l;
}

// ---------------- fused pre-LN for q/k/v + gate (bf16 hi/lo out) -------------
__global__ __launch_bounds__(256) void ln3_kernel(
    const float* __restrict__ q, const float* __restrict__ k, const float* __restrict__ v,
    const float* __restrict__ gq, const float* __restrict__ bq,
    const float* __restrict__ gkv, const float* __restrict__ bkv,
    const float* __restrict__ Wg,
    bf16* __restrict__ oqh, bf16* __restrict__ oql,
    bf16* __restrict__ okh, bf16* __restrict__ okl,
    bf16* __restrict__ ovh, bf16* __restrict__ ovl,
    float* __restrict__ gate)
{
    const int row = blockIdx.x, src = blockIdx.y;
    const float* x  = src == 0 ? q  : (src == 1 ? k  : v);
    bf16* outh = src == 0 ? oqh : (src == 1 ? okh : ovh);
    bf16* outl = src == 0 ? oql : (src == 1 ? okl : ovl);
    const float* gg = src == 0 ? gq : gkv;
    const float* bb = src == 0 ? bq : bkv;
    const int tid = threadIdx.x, lane = tid & 31, warp = tid >> 5;

    float4 xv = ((const float4*)(x + (size_t)row*DM))[tid];
    float s  = xv.x + xv.y + xv.z + xv.w;
    float ss = xv.x*xv.x + xv.y*xv.y + xv.z*xv.z + xv.w*xv.w;

    __shared__ __align__(16) float red[16];
    #pragma unroll
    for (int off = 16; off; off >>= 1) {
        s  += __shfl_xor_sync(0xffffffffu, s,  off);
        ss += __shfl_xor_sync(0xffffffffu, ss, off);
    }
    if (lane == 0) { red[warp] = s; red[8 + warp] = ss; }
    __syncthreads();
    float st = 0.f, sst = 0.f;
    #pragma unroll
    for (int i = 0; i < 8; i++) { st += red[i]; sst += red[8 + i]; }
    float mu   = st * (1.f/DM);
    float var  = sst * (1.f/DM) - mu*mu;
    float rstd = rsqrtf(var + EPS);

    float4 gv = ((const float4*)gg)[tid];
    float4 bv = ((const float4*)bb)[tid];
    float4 yv;
    yv.x = (xv.x - mu)*rstd*gv.x + bv.x;
    yv.y = (xv.y - mu)*rstd*gv.y + bv.y;
    yv.z = (xv.z - mu)*rstd*gv.z + bv.z;
    yv.w = (xv.w - mu)*rstd*gv.w + bv.w;
    uint2 hh, ll; split4b(yv, hh, ll);
    *(uint2*)&outh[(size_t)row*DM + tid*4] = hh;
    *(uint2*)&outl[(size_t)row*DM + tid*4] = ll;

    if (src == 0) {  // gate = sigmoid(qn . Wg)
        float4 wv = ((const float4*)Wg)[tid];
        float gp = yv.x*wv.x + yv.y*wv.y + yv.z*wv.z + yv.w*wv.w;
        #pragma unroll
        for (int off = 16; off; off >>= 1) gp += __shfl_xor_sync(0xffffffffu, gp, off);
        __syncthreads();
        if (lane == 0) red[warp] = gp;
        __syncthreads();
        if (tid == 0) {
            float t = 0.f;
            #pragma unroll
            for (int i = 0; i < 8; i++) t += red[i];
            gate[row] = 1.f / (1.f + __expf(-t));
        }
    }
}

// ---------------- 3xBF16 GEMM: pre-split A AND B; pure-copy staging ----------
// BM=128, BN=64, BK=32. 256 threads, 8 warps (4m x 2n), warp tile 32x32.
#define AST 40
#define BST 72
#define GBUF (128*AST*2 + 32*BST*2)   /* elems per buffer = 14848 (29,696 B) */
#define GEMM_SMEM (2*GBUF*2)          /* bytes = 59,392 */
__global__ __launch_bounds__(256, 2) void gemm_bf16x3(
    const bf16* __restrict__ Ah0, const bf16* __restrict__ Al0,
    const bf16* __restrict__ Ah1, const bf16* __restrict__ Al1,
    const bf16* __restrict__ Ah2, const bf16* __restrict__ Al2,
    const bf16* __restrict__ Wh_base, const bf16* __restrict__ Wl_base, int woff,
    const float* __restrict__ b0, const float* __restrict__ b1, const float* __restrict__ b2,
    const float* __restrict__ gate, float* __restrict__ Cf,
    bf16* __restrict__ Ch0, bf16* __restrict__ Cl0,
    bf16* __restrict__ Ch1, bf16* __restrict__ Cl1,
    bf16* __restrict__ Ch2, bf16* __restrict__ Cl2)
{
    extern __shared__ __align__(16) bf16 gsm[];

    const int z = blockIdx.z;
    const bf16* Ah_g = z == 0 ? Ah0 : (z == 1 ? Ah1 : Ah2);
    const bf16* Al_g = z == 0 ? Al0 : (z == 1 ? Al1 : Al2);
    const float* bias = z == 0 ? b0 : (z == 1 ? b1 : b2);
    bf16* Ch = z == 0 ? Ch0 : (z == 1 ? Ch1 : Ch2);
    bf16* Cl = z == 0 ? Cl0 : (z == 1 ? Cl1 : Cl2);
    const bf16* Wh_g = Wh_base + (size_t)(woff + z)*DM*DM;
    const bf16* Wl_g = Wl_base + (size_t)(woff + z)*DM*DM;

    const int tid = threadIdx.x, lane = tid & 31, warp = tid >> 5;
    const int bm = blockIdx.y * 128, bn = blockIdx.x * 64;
    const int wm = (warp >> 1) * 32, wn = (warp & 1) * 32;

    float acc[2][4][4] = {};
    uint4 pa_h[2], pa_l[2], pb_h, pb_l;

    // A tile 128x32 bf16 = 512 uint4 chunks; 2/thread/array
    const int ar = tid >> 2, ac = (tid & 3) * 8;
    // B tile 32x64 bf16 = 256 chunks; 1/thread/array
    const int br = tid >> 3, bc = (tid & 7) * 8;

    auto loadT = [&](int k0) {
        #pragma unroll
        for (int i = 0; i < 2; i++) {
            int r = ar + i*64;
            pa_h[i] = *(const uint4*)(Ah_g + (size_t)(bm + r)*DM + k0 + ac);
            pa_l[i] = *(const uint4*)(Al_g + (size_t)(bm + r)*DM + k0 + ac);
        }
        pb_h = *(const uint4*)(Wh_g + (size_t)(k0 + br)*DM + bn + bc);
        pb_l = *(const uint4*)(Wl_g + (size_t)(k0 + br)*DM + bn + bc);
    };
    auto storeT = [&](int buf) {
        bf16* Ah = gsm + buf*GBUF;
        bf16* Al = Ah + 128*AST;
        bf16* Bh = Al + 128*AST;
        bf16* Bl = Bh + 32*BST;
        #pragma unroll
        for (int i = 0; i < 2; i++) {
            int r = ar + i*64;
            *(uint4*)&Ah[r*AST + ac] = pa_h[i];
            *(uint4*)&Al[r*AST + ac] = pa_l[i];
        }
        *(uint4*)&Bh[br*BST + bc] = pb_h;
        *(uint4*)&Bl[br*BST + bc] = pb_l;
    };

    loadT(0); storeT(0); __syncthreads();

    for (int t = 0; t < 32; t++) {
        const int cur = t & 1;
        if (t + 1 < 32) loadT((t + 1) * 32);

        const uint32_t base = smem_u32(gsm + cur*GBUF);
        const uint32_t ah_b = base;
        const uint32_t al_b = base + 128*AST*2;
        const uint32_t bh_b = base + 128*AST*4;
        const uint32_t bl_b = bh_b + 32*BST*2;

        #pragma unroll
        for (int kc = 0; kc < 2; kc++) {
            uint32_t af_h[2][4], af_l[2][4];
            #pragma unroll
            for (int mi = 0; mi < 2; mi++) {
                uint32_t off = ((wm + mi*16 + (lane & 15))*AST + kc*16 + (lane >> 4)*8) * 2;
                ldmx4(af_h[mi], ah_b + off);
                ldmx4(af_l[mi], al_b + off);
            }
            uint32_t bf_h[2][4], bf_l[2][4];
            #pragma unroll
            for (int nip = 0; nip < 2; nip++) {
                uint32_t off = ((kc*16 + (lane & 15))*BST + wn + nip*16 + (lane >> 4)*8) * 2;
                ldmx4t(bf_h[nip], bh_b + off);
                ldmx4t(bf_l[nip], bl_b + off);
            }
            #pragma unroll
            for (int mi = 0; mi < 2; mi++)
                #pragma unroll
                for (int ni = 0; ni < 4; ni++) {
                    const uint32_t* b2h = &bf_h[ni >> 1][(ni & 1)*2];
                    const uint32_t* b2l = &bf_l[ni >> 1][(ni & 1)*2];
                    mma_bf16(acc[mi][ni], af_h[mi], b2h);
                    mma_bf16(acc[mi][ni], af_l[mi], b2h);
                    mma_bf16(acc[mi][ni], af_h[mi], b2l);
                }
        }

        if (t + 1 < 32) {
            storeT(1 - cur);
            __syncthreads();
        }
    }

    #pragma unroll
    for (int mi = 0; mi < 2; mi++) {
        #pragma unroll
        for (int ni = 0; ni < 4; ni++) {
            int r0 = bm + wm + mi*16 + (lane >> 2);
            int c0 = bn + wn + ni*8 + 2*(lane & 3);
            float bz0 = bias[c0], bz1 = bias[c0 + 1];
            float v0 = acc[mi][ni][0] + bz0;
            float v1 = acc[mi][ni][1] + bz1;
            float v2 = acc[mi][ni][2] + bz0;
            float v3 = acc[mi][ni][3] + bz1;
            if (Cf) {
                float gA = gate[r0], gB = gate[r0 + 8];
                Cf[(size_t)r0*DM + c0]         = v0*gA;
                Cf[(size_t)r0*DM + c0 + 1]     = v1*gA;
                Cf[(size_t)(r0+8)*DM + c0]     = v2*gB;
                Cf[(size_t)(r0+8)*DM + c0 + 1] = v3*gB;
            } else {
                float h0 = hi_bf16(v0), h1 = hi_bf16(v1);
                float h2 = hi_bf16(v2), h3 = hi_bf16(v3);
                *(uint32_t*)&Ch[(size_t)r0*DM + c0]     = packb(h0, h1);
                *(uint32_t*)&Ch[(size_t)(r0+8)*DM + c0] = packb(h2, h3);
                *(uint32_t*)&Cl[(size_t)r0*DM + c0]     = packb(v0 - h0, v1 - h1);
                *(uint32_t*)&Cl[(size_t)(r0+8)*DM + c0] = packb(v2 - h2, v3 - h3);
            }
        }
    }
}

// ---------------- flash attention: 128 q-rows, pre-split I/O (R14 core) ------
#define KST 72
#define KVBUF (4*64*KST)       /* elems per buffer = 18432 (36,864 B) */
#define ATTN_SMEM (2*KVBUF*2)  /* bytes = 73,728 */
#define LOG2E 1.44269504088896f
__global__ __launch_bounds__(256, 1) void attn_bf16(
    const bf16* __restrict__ Qh_g, const bf16* __restrict__ Ql_g,
    const bf16* __restrict__ Kh_g, const bf16* __restrict__ Kl_g,
    const bf16* __restrict__ Vh_g, const bf16* __restrict__ Vl_g,
    bf16* __restrict__ Oh_g, bf16* __restrict__ Ol_g)
{
    extern __shared__ __align__(16) bf16 asm_[];
    bf16* Qh = asm_;                 // 128*KST (aliases KV buffer 0)
    bf16* Ql = asm_ + 128*KST;

    const int tid = threadIdx.x, lane = tid & 31, warp = tid >> 5;
    const int qt = blockIdx.x, h = blockIdx.y, b = blockIdx.z;
    const size_t qrow0 = (size_t)(b*SEQ + qt*128);
    const size_t kvrow0 = (size_t)(b*SEQ);
    const int hc = h * HD;

    // stage pre-split Q tile 128x64 (pure copy)
    #pragma unroll
    for (int i = 0; i < 4; i++) {
        int idx = tid + i*256;
        int r = idx >> 3, c8 = (idx & 7) * 8;
        *(uint4*)&Qh[r*KST + c8] = *(const uint4*)(Qh_g + (qrow0 + r)*DM + hc + c8);
        *(uint4*)&Ql[r*KST + c8] = *(const uint4*)(Ql_g + (qrow0 + r)*DM + hc + c8);
    }
    __syncthreads();

    uint32_t qh[4][4], ql[4][4];
    {
        const uint32_t qh_b = smem_u32(Qh), ql_b = smem_u32(Ql);
        #pragma unroll
        for (int kc = 0; kc < 4; kc++) {
            uint32_t off = ((warp*16 + (lane & 15))*KST + kc*16 + (lane >> 4)*8) * 2;
            ldmx4(qh[kc], qh_b + off);
            ldmx4(ql[kc], ql_b + off);
        }
    }
    __syncthreads();   // Q frags in regs; buffer 0 may now be overwritten

    float o[8][4] = {};
    float mrow[2] = {-1e30f, -1e30f};
    float lrow[2] = {0.f, 0.f};

    uint4 pkh[2], pkl[2], pvh[2], pvl[2];
    auto loadKV = [&](int t) {
        #pragma unroll
        for (int i = 0; i < 2; i++) {
            int idx = tid + i*256;
            int r = idx >> 3, c8 = (idx & 7) * 8;
            const size_t g = (kvrow0 + t*64 + r)*DM + hc + c8;
            pkh[i] = *(const uint4*)(Kh_g + g);
            pkl[i] = *(const uint4*)(Kl_g + g);
            pvh[i] = *(const uint4*)(Vh_g + g);
            pvl[i] = *(const uint4*)(Vl_g + g);
        }
    };
    auto storeKV = [&](int buf) {
        bf16* Kh = asm_ + buf*KVBUF;
        bf16* Kl = Kh + 64*KST;
        bf16* Vh = Kl + 64*KST;
        bf16* Vl = Vh + 64*KST;
        #pragma unroll
        for (int i = 0; i < 2; i++) {
            int idx = tid + i*256;
            int r = idx >> 3, c8 = (idx & 7) * 8;
            *(uint4*)&Kh[r*KST + c8] = pkh[i];
            *(uint4*)&Kl[r*KST + c8] = pkl[i];
            *(uint4*)&Vh[r*KST + c8] = pvh[i];
            *(uint4*)&Vl[r*KST + c8] = pvl[i];
        }
    };

    loadKV(0); storeKV(0); __syncthreads();

    for (int t = 0; t < SEQ/64; t++) {
        const int cur = t & 1;
        if (t + 1 < SEQ/64) loadKV(t + 1);

        const uint32_t base = smem_u32(asm_ + cur*KVBUF);
        const uint32_t kh_b = base;
        const uint32_t kl_b = base + 64*KST*2;
        const uint32_t vh_b = base + 64*KST*4;
        const uint32_t vl_b = base + 64*KST*6;

        // ---- S = Q K^T (3xBF16) ----
        float s[8][4] = {};
        #pragma unroll
        for (int kc = 0; kc < 4; kc++) {
            #pragma unroll
            for (int nip = 0; nip < 4; nip++) {
                uint32_t off = ((nip*16 + (lane >> 4)*8 + (lane & 7))*KST
                                + kc*16 + ((lane >> 3) & 1)*8) * 2;
                uint32_t kf_h[4], kf_l[4];
                ldmx4(kf_h, kh_b + off);
                ldmx4(kf_l, kl_b + off);
                #pragma unroll
                for (int hf = 0; hf < 2; hf++) {
                    int ni = nip*2 + hf;
                    mma_bf16(s[ni], qh[kc], &kf_h[hf*2]);
                    mma_bf16(s[ni], ql[kc], &kf_h[hf*2]);
                    mma_bf16(s[ni], qh[kc], &kf_l[hf*2]);
                }
            }
        }
        #pragma unroll
        for (int ni = 0; ni < 8; ni++) {     // fold softmax scale * log2e
            s[ni][0] *= 0.125f*LOG2E; s[ni][1] *= 0.125f*LOG2E;
            s[ni][2] *= 0.125f*LOG2E; s[ni][3] *= 0.125f*LOG2E;
        }

        // ---- online softmax per row-half (base-2 domain) ----
        #pragma unroll
        for (int rh = 0; rh < 2; rh++) {
            float mx = -1e30f;
            #pragma unroll
            for (int ni = 0; ni < 8; ni++)
                mx = fmaxf(mx, fmaxf(s[ni][rh*2], s[ni][rh*2+1]));
            mx = fmaxf(mx, __shfl_xor_sync(0xffffffffu, mx, 1));
            mx = fmaxf(mx, __shfl_xor_sync(0xffffffffu, mx, 2));
            float mnew  = fmaxf(mrow[rh], mx);
            float alpha = exp2f(mrow[rh] - mnew);
            mrow[rh] = mnew;
            float sum = 0.f;
            #pragma unroll
            for (int ni = 0; ni < 8; ni++) {
                s[ni][rh*2]   = exp2f(s[ni][rh*2]   - mnew);
                s[ni][rh*2+1] = exp2f(s[ni][rh*2+1] - mnew);
                sum += s[ni][rh*2] + s[ni][rh*2+1];
            }
            sum += __shfl_xor_sync(0xffffffffu, sum, 1);
            sum += __shfl_xor_sync(0xffffffffu, sum, 2);
            lrow[rh] = lrow[rh]*alpha + sum;
            #pragma unroll
            for (int ni = 0; ni < 8; ni++) { o[ni][rh*2] *= alpha; o[ni][rh*2+1] *= alpha; }
        }

        // ---- O += P V (3xBF16); P fragments built directly from s regs ----
        #pragma unroll
        for (int kcp = 0; kcp < 4; kcp++) {
            uint32_t pa_h[4], pa_l[4];
            #pragma unroll
            for (int j = 0; j < 2; j++) {
                float e0 = s[2*kcp + j][0], e1 = s[2*kcp + j][1];
                float e2 = s[2*kcp + j][2], e3 = s[2*kcp + j][3];
                float h0 = hi_bf16(e0), h1 = hi_bf16(e1), h2 = hi_bf16(e2), h3 = hi_bf16(e3);
                pa_h[2*j]   = packb(h0, h1);
                pa_h[2*j+1] = packb(h2, h3);
                pa_l[2*j]   = packb(e0 - h0, e1 - h1);
                pa_l[2*j+1] = packb(e2 - h2, e3 - h3);
            }
            #pragma unroll
            for (int nip = 0; nip < 4; nip++) {
                uint32_t off = ((kcp*16 + ((lane >> 3) & 1)*8 + (lane & 7))*KST
                                + nip*16 + (lane >> 4)*8) * 2;
                uint32_t vf_h[4], vf_l[4];
                ldmx4t(vf_h, vh_b + off);
                ldmx4t(vf_l, vl_b + off);
                #pragma unroll
                for (int hf = 0; hf < 2; hf++) {
                    int ni = nip*2 + hf;
                    mma_bf16(o[ni], pa_h, &vf_h[hf*2]);
                    mma_bf16(o[ni], pa_l, &vf_h[hf*2]);
                    mma_bf16(o[ni], pa_h, &vf_l[hf*2]);
                }
            }
        }

        if (t + 1 < SEQ/64) {
            storeKV(1 - cur);
            __syncthreads();
        }
    }

    // epilogue: normalize, split hi/lo, packed STG.32 (pairs are contiguous)
    float inv0 = 1.f / lrow[0], inv1 = 1.f / lrow[1];
    int r = warp*16 + (lane >> 2);
    #pragma unroll
    for (int ni = 0; ni < 8; ni++) {
        int c = ni*8 + 2*(lane & 3);
        float v0 = o[ni][0]*inv0, v1 = o[ni][1]*inv0;
        float v2 = o[ni][2]*inv1, v3 = o[ni][3]*inv1;
        float h0 = hi_bf16(v0), h1 = hi_bf16(v1), h2 = hi_bf16(v2), h3 = hi_bf16(v3);
        size_t p0 = (qrow0 + r)*DM + hc + c;
        size_t p1 = (qrow0 + r + 8)*DM + hc + c;
        *(uint32_t*)&Oh_g[p0] = packb(h0, h1);
        *(uint32_t*)&Oh_g[p1] = packb(h2, h3);
        *(uint32_t*)&Ol_g[p0] = packb(v0 - h0, v1 - h1);
        *(uint32_t*)&Ol_g[p1] = packb(v2 - h2, v3 - h3);
    }
}

// ---------------- final LN ---------------------------------------------------
__global__ __launch_bounds__(256) void ln_out_kernel(
    const float* __restrict__ x, const float* __restrict__ gg,
    const float* __restrict__ bb, float* __restrict__ out)
{
    const int row = blockIdx.x;
    const int tid = threadIdx.x, lane = tid & 31, warp = tid >> 5;
    float4 xv = ((const float4*)(x + (size_t)row*DM))[tid];
    float s  = xv.x + xv.y + xv.z + xv.w;
    float ss = xv.x*xv.x + xv.y*xv.y + xv.z*xv.z + xv.w*xv.w;
    __shared__ __align__(16) float red[16];
    #pragma unroll
    for (int off = 16; off; off >>= 1) {
        s  += __shfl_xor_sync(0xffffffffu, s,  off);
        ss += __shfl_xor_sync(0xffffffffu, ss, off);
    }
    if (lane == 0) { red[warp] = s; red[8 + warp] = ss; }
    __syncthreads();
    float st = 0.f, sst = 0.f;
    #pragma unroll
    for (int i = 0; i < 8; i++) { st += red[i]; sst += red[8 + i]; }
    float mu   = st * (1.f/DM);
    float var  = sst * (1.f/DM) - mu*mu;
    float rstd = rsqrtf(var + EPS);
    float4 gv = ((const float4*)gg)[tid];
    float4 bv = ((const float4*)bb)[tid];
    float4 yv;
    yv.x = (xv.x - mu)*rstd*gv.x + bv.x;
    yv.y = (xv.y - mu)*rstd*gv.y + bv.y;
    yv.z = (xv.z - mu)*rstd*gv.z + bv.z;
    yv.w = (xv.w - mu)*rstd*gv.w + bv.w;
    ((float4*)(out + (size_t)row*DM))[tid] = yv;
}

// ---------------- launch -----------------------------------------------------
extern "C" void kernel_launch(void* const* d_in, const int* in_sizes, int n_in,
                              void* d_out, int out_size) {
    const float* query  = (const float*)d_in[0];
    const float* key_   = (const float*)d_in[1];
    const float* value  = (const float*)d_in[2];
    const float* Wq     = (const float*)d_in[3];
    const float* bq     = (const float*)d_in[4];
    const float* Wk     = (const float*)d_in[5];
    const float* bk     = (const float*)d_in[6];
    const float* Wv     = (const float*)d_in[7];
    const float* bv     = (const float*)d_in[8];
    const float* Wo     = (const float*)d_in[9];
    const float* bo     = (const float*)d_in[10];
    const float* Wg     = (const float*)d_in[11];
    const float* ln_q_g = (const float*)d_in[12];
    const float* ln_q_b = (const float*)d_in[13];
    const float* ln_kv_g= (const float*)d_in[14];
    const float* ln_kv_b= (const float*)d_in[15];
    const float* ln_o_g = (const float*)d_in[16];
    const float* ln_o_b = (const float*)d_in[17];

    float *y, *gate;
    bf16 *wh, *wl, *qnh, *qnl, *knh, *knl, *vnh, *vnl;
    bf16 *qph, *qpl, *kph, *kpl, *vph, *vpl, *aoh, *aol;
    cudaGetSymbolAddress((void**)&y,   g_y);
    cudaGetSymbolAddress((void**)&gate,g_gate);
    cudaGetSymbolAddress((void**)&wh,  g_wh);
    cudaGetSymbolAddress((void**)&wl,  g_wl);
    cudaGetSymbolAddress((void**)&qnh, g_qnh); cudaGetSymbolAddress((void**)&qnl, g_qnl);
    cudaGetSymbolAddress((void**)&knh, g_knh); cudaGetSymbolAddress((void**)&knl, g_knl);
    cudaGetSymbolAddress((void**)&vnh, g_vnh); cudaGetSymbolAddress((void**)&vnl, g_vnl);
    cudaGetSymbolAddress((void**)&qph, g_qph); cudaGetSymbolAddress((void**)&qpl, g_qpl);
    cudaGetSymbolAddress((void**)&kph, g_kph); cudaGetSymbolAddress((void**)&kpl, g_kpl);
    cudaGetSymbolAddress((void**)&vph, g_vph); cudaGetSymbolAddress((void**)&vpl, g_vpl);
    cudaGetSymbolAddress((void**)&aoh, g_aoh); cudaGetSymbolAddress((void**)&aol, g_aol);

    bf16* whm[4] = {wh, wh + (size_t)DM*DM, wh + 2*(size_t)DM*DM, wh + 3*(size_t)DM*DM};
    bf16* wlm[4] = {wl, wl + (size_t)DM*DM, wl + 2*(size_t)DM*DM, wl + 3*(size_t)DM*DM};

    cudaFuncSetAttribute(gemm_bf16x3, cudaFuncAttributeMaxDynamicSharedMemorySize, GEMM_SMEM);
    cudaFuncSetAttribute(attn_bf16,  cudaFuncAttributeMaxDynamicSharedMemorySize, ATTN_SMEM);

    splitw_kernel<<<dim3(1024, 4), 256>>>(Wq, Wk, Wv, Wo,
        whm[0], wlm[0], whm[1], wlm[1], whm[2], wlm[2], whm[3], wlm[3]);
    ln3_kernel<<<dim3(MTOT, 3), 256>>>(query, key_, value,
                                       ln_q_g, ln_q_b, ln_kv_g, ln_kv_b, Wg,
                                       qnh, qnl, knh, knl, vnh, vnl, gate);
    // merged QKV projections (pre-split A) -> packed bf16 hi/lo outputs
    gemm_bf16x3<<<dim3(16, 64, 3), 256, GEMM_SMEM>>>(
        qnh, qnl, knh, knl, vnh, vnl, wh, wl, 0,
        bq, bk, bv, nullptr, nullptr,
        qph, qpl, kph, kpl, vph, vpl);
    attn_bf16<<<dim3(SEQ/128, NH, BATCH), 256, ATTN_SMEM>>>(qph, qpl, kph, kpl, vph, vpl, aoh, aol);
    // output projection (pre-split A from attention) with gate epilogue (fp32 out)
    gemm_bf16x3<<<dim3(16, 64, 1), 256, GEMM_SMEM>>>(
        aoh, aol, aoh, aol, aoh, aol, wh, wl, 3,
        bo, bo, bo, gate, y,
        nullptr, nullptr, nullptr, nullptr, nullptr, nullptr);
    ln_out_kernel<<<MTOT, 256>>>(y, ln_o_g, ln_o_b, (float*)d_out);
}

// round 17
// speedup vs baseline: 1.0756x; 1.0405x over previous
#include <cuda_runtime.h>
#include <cuda_bf16.h>
#include <cstdint>

#define DM   1024
#define BATCH 4
#define SEQ  2048
#define NH   16
#define HD   64
#define MTOT (BATCH*SEQ)   /* 8192 */
#define EPS  1e-5f
#define QSCALE (0.125f*1.44269504088896f)   /* softmax scale * log2e, folded into Q */

typedef __nv_bfloat16 bf16;

// ---------------- scratch (device globals; no allocations allowed) ----------
__device__ float g_qn[MTOT*DM];
__device__ float g_kn[MTOT*DM];
__device__ float g_vn[MTOT*DM];
__device__ bf16  g_wh[4][DM*DM], g_wl[4][DM*DM];   /* pre-split weights [K][N] */
__device__ bf16  g_qph[MTOT*DM], g_qpl[MTOT*DM];   /* pre-split projections   */
__device__ bf16  g_kph[MTOT*DM], g_kpl[MTOT*DM];
__device__ bf16  g_vph[MTOT*DM], g_vpl[MTOT*DM];
__device__ float g_ao[MTOT*DM];
__device__ float g_y [MTOT*DM];
__device__ float g_gate[MTOT];

// ---------------- bf16 mma m16n8k16 + ldmatrix helpers ----------------------
__device__ __forceinline__ void mma_bf16(float c[4], const uint32_t a[4], const uint32_t b[2]) {
    asm volatile(
        "mma.sync.aligned.m16n8k16.row.col.f32.bf16.bf16.f32 "
        "{%0,%1,%2,%3}, {%4,%5,%6,%7}, {%8,%9}, {%0,%1,%2,%3};\n"
        : "+f"(c[0]), "+f"(c[1]), "+f"(c[2]), "+f"(c[3])
        : "r"(a[0]), "r"(a[1]), "r"(a[2]), "r"(a[3]), "r"(b[0]), "r"(b[1]));
}
__device__ __forceinline__ uint32_t smem_u32(const void* p) {
    return (uint32_t)__cvta_generic_to_shared(p);
}
__device__ __forceinline__ void ldmx4(uint32_t r[4], uint32_t addr) {
    asm volatile("ldmatrix.sync.aligned.m8n8.x4.shared.b16 {%0,%1,%2,%3}, [%4];"
                 : "=r"(r[0]), "=r"(r[1]), "=r"(r[2]), "=r"(r[3]) : "r"(addr));
}
__device__ __forceinline__ void ldmx4t(uint32_t r[4], uint32_t addr) {
    asm volatile("ldmatrix.sync.aligned.m8n8.x4.trans.shared.b16 {%0,%1,%2,%3}, [%4];"
                 : "=r"(r[0]), "=r"(r[1]), "=r"(r[2]), "=r"(r[3]) : "r"(addr));
}
__device__ __forceinline__ uint32_t packb(float e0, float e1) {
    uint32_t r;
    asm("cvt.rn.bf16x2.f32 %0, %1, %2;" : "=r"(r) : "f"(e1), "f"(e0));
    return r;
}
__device__ __forceinline__ float hi_bf16(float x) {
    return __bfloat162float(__float2bfloat16(x));
}
__device__ __forceinline__ void split4b(float4 v, uint2& h, uint2& l) {
    float hx = hi_bf16(v.x), hy = hi_bf16(v.y), hz = hi_bf16(v.z), hw = hi_bf16(v.w);
    h.x = packb(hx, hy); h.y = packb(hz, hw);
    l.x = packb(v.x - hx, v.y - hy); l.y = packb(v.z - hz, v.w - hw);
}

// ---------------- weight split: f32 -> bf16 hi/lo (layout preserved [K][N]) --
__global__ __launch_bounds__(256) void splitw_kernel(
    const float* __restrict__ W0, const float* __restrict__ W1,
    const float* __restrict__ W2, const float* __restrict__ W3,
    bf16* __restrict__ H0, bf16* __restrict__ L0,
    bf16* __restrict__ H1, bf16* __restrict__ L1,
    bf16* __restrict__ H2, bf16* __restrict__ L2,
    bf16* __restrict__ H3, bf16* __restrict__ L3)
{
    const float* W[4] = {W0, W1, W2, W3};
    bf16* H[4] = {H0, H1, H2, H3};
    bf16* L[4] = {L0, L1, L2, L3};
    int m = blockIdx.y;
    int i = blockIdx.x * 256 + threadIdx.x;          // float4 index
    float4 v = ((const float4*)W[m])[i];
    uint2 h, l; split4b(v, h, l);
    *(uint2*)&H[m][(size_t)i*4] = h;
    *(uint2*)&L[m][(size_t)i*4] = l;
}

// ---------------- fused pre-LN for q/k/v + gate (fp32 out) -------------------
__global__ __launch_bounds__(256) void ln3_kernel(
    const float* __restrict__ q, const float* __restrict__ k, const float* __restrict__ v,
    const float* __restrict__ gq, const float* __restrict__ bq,
    const float* __restrict__ gkv, const float* __restrict__ bkv,
    const float* __restrict__ Wg,
    float* __restrict__ oq, float* __restrict__ ok, float* __restrict__ ov,
    float* __restrict__ gate)
{
    const int row = blockIdx.x, src = blockIdx.y;
    const float* x  = src == 0 ? q  : (src == 1 ? k  : v);
    float*       out= src == 0 ? oq : (src == 1 ? ok : ov);
    const float* gg = src == 0 ? gq : gkv;
    const float* bb = src == 0 ? bq : bkv;
    const int tid = threadIdx.x, lane = tid & 31, warp = tid >> 5;

    float4 xv = ((const float4*)(x + (size_t)row*DM))[tid];
    float s  = xv.x + xv.y + xv.z + xv.w;
    float ss = xv.x*xv.x + xv.y*xv.y + xv.z*xv.z + xv.w*xv.w;

    __shared__ __align__(16) float red[16];
    #pragma unroll
    for (int off = 16; off; off >>= 1) {
        s  += __shfl_xor_sync(0xffffffffu, s,  off);
        ss += __shfl_xor_sync(0xffffffffu, ss, off);
    }
    if (lane == 0) { red[warp] = s; red[8 + warp] = ss; }
    __syncthreads();
    float st = 0.f, sst = 0.f;
    #pragma unroll
    for (int i = 0; i < 8; i++) { st += red[i]; sst += red[8 + i]; }
    float mu   = st * (1.f/DM);
    float var  = sst * (1.f/DM) - mu*mu;
    float rstd = rsqrtf(var + EPS);

    float4 gv = ((const float4*)gg)[tid];
    float4 bv = ((const float4*)bb)[tid];
    float4 yv;
    yv.x = (xv.x - mu)*rstd*gv.x + bv.x;
    yv.y = (xv.y - mu)*rstd*gv.y + bv.y;
    yv.z = (xv.z - mu)*rstd*gv.z + bv.z;
    yv.w = (xv.w - mu)*rstd*gv.w + bv.w;
    ((float4*)(out + (size_t)row*DM))[tid] = yv;

    if (src == 0) {  // gate = sigmoid(qn . Wg)
        float4 wv = ((const float4*)Wg)[tid];
        float gp = yv.x*wv.x + yv.y*wv.y + yv.z*wv.z + yv.w*wv.w;
        #pragma unroll
        for (int off = 16; off; off >>= 1) gp += __shfl_xor_sync(0xffffffffu, gp, off);
        __syncthreads();
        if (lane == 0) red[warp] = gp;
        __syncthreads();
        if (tid == 0) {
            float t = 0.f;
            #pragma unroll
            for (int i = 0; i < 8; i++) t += red[i];
            gate[row] = 1.f / (1.f + __expf(-t));
        }
    }
}

// ---------------- 3xBF16 GEMM, double-buffered; dual epilogue ----------------
// BM=128, BN=64, BK=32. 256 threads, 8 warps (4m x 2n), warp tile 32x32.
// Cf != null : fp32 output with gate.  Cf == null : packed bf16 hi/lo output,
//              scaled by QSCALE for z==0 (Q projection carries softmax scale).
#define AST 40
#define BST 72
#define GBUF (128*AST*2 + 32*BST*2)   /* elems per buffer = 14848 (29,696 B) */
#define GEMM_SMEM (2*GBUF*2)          /* bytes = 59,392 */
__global__ __launch_bounds__(256, 2) void gemm_bf16x3(
    const float* __restrict__ A0, const float* __restrict__ A1, const float* __restrict__ A2,
    const bf16* __restrict__ Wh_base, const bf16* __restrict__ Wl_base, int woff,
    const float* __restrict__ b0, const float* __restrict__ b1, const float* __restrict__ b2,
    const float* __restrict__ gate, float* __restrict__ Cf,
    bf16* __restrict__ Ch0, bf16* __restrict__ Cl0,
    bf16* __restrict__ Ch1, bf16* __restrict__ Cl1,
    bf16* __restrict__ Ch2, bf16* __restrict__ Cl2)
{
    extern __shared__ __align__(16) bf16 gsm[];

    const int z = blockIdx.z;
    const float* A    = z == 0 ? A0 : (z == 1 ? A1 : A2);
    const float* bias = z == 0 ? b0 : (z == 1 ? b1 : b2);
    bf16* Ch = z == 0 ? Ch0 : (z == 1 ? Ch1 : Ch2);
    bf16* Cl = z == 0 ? Cl0 : (z == 1 ? Cl1 : Cl2);
    const bf16* Wh_g = Wh_base + (size_t)(woff + z)*DM*DM;
    const bf16* Wl_g = Wl_base + (size_t)(woff + z)*DM*DM;

    const int tid = threadIdx.x, lane = tid & 31, warp = tid >> 5;
    const int bm = blockIdx.y * 128, bn = blockIdx.x * 64;
    const int wm = (warp >> 1) * 32, wn = (warp & 1) * 32;

    float acc[2][4][4] = {};
    float4 pa[4];
    uint4 pb_h, pb_l;

    const int br = tid >> 3, bc = (tid & 7) * 8;

    auto loadT = [&](int k0) {
        #pragma unroll
        for (int i = 0; i < 4; i++) {
            int idx = (tid + i*256) * 4;
            int m = idx >> 5, kk = idx & 31;
            pa[i] = *(const float4*)(A + (size_t)(bm + m)*1024 + k0 + kk);
        }
        pb_h = *(const uint4*)(Wh_g + (size_t)(k0 + br)*DM + bn + bc);
        pb_l = *(const uint4*)(Wl_g + (size_t)(k0 + br)*DM + bn + bc);
    };
    auto storeT = [&](int buf) {
        bf16* Ah = gsm + buf*GBUF;
        bf16* Al = Ah + 128*AST;
        bf16* Bh = Al + 128*AST;
        bf16* Bl = Bh + 32*BST;
        #pragma unroll
        for (int i = 0; i < 4; i++) {
            int idx = (tid + i*256) * 4;
            int m = idx >> 5, kk = idx & 31;
            uint2 h, l; split4b(pa[i], h, l);
            *(uint2*)&Ah[m*AST + kk] = h;
            *(uint2*)&Al[m*AST + kk] = l;
        }
        *(uint4*)&Bh[br*BST + bc] = pb_h;
        *(uint4*)&Bl[br*BST + bc] = pb_l;
    };

    loadT(0); storeT(0); __syncthreads();

    for (int t = 0; t < 32; t++) {
        const int cur = t & 1;
        if (t + 1 < 32) loadT((t + 1) * 32);

        const uint32_t base = smem_u32(gsm + cur*GBUF);
        const uint32_t ah_b = base;
        const uint32_t al_b = base + 128*AST*2;
        const uint32_t bh_b = base + 128*AST*4;
        const uint32_t bl_b = bh_b + 32*BST*2;

        #pragma unroll
        for (int kc = 0; kc < 2; kc++) {
            uint32_t af_h[2][4], af_l[2][4];
            #pragma unroll
            for (int mi = 0; mi < 2; mi++) {
                uint32_t off = ((wm + mi*16 + (lane & 15))*AST + kc*16 + (lane >> 4)*8) * 2;
                ldmx4(af_h[mi], ah_b + off);
                ldmx4(af_l[mi], al_b + off);
            }
            uint32_t bf_h[2][4], bf_l[2][4];
            #pragma unroll
            for (int nip = 0; nip < 2; nip++) {
                uint32_t off = ((kc*16 + (lane & 15))*BST + wn + nip*16 + (lane >> 4)*8) * 2;
                ldmx4t(bf_h[nip], bh_b + off);
                ldmx4t(bf_l[nip], bl_b + off);
            }
            #pragma unroll
            for (int mi = 0; mi < 2; mi++)
                #pragma unroll
                for (int ni = 0; ni < 4; ni++) {
                    const uint32_t* b2h = &bf_h[ni >> 1][(ni & 1)*2];
                    const uint32_t* b2l = &bf_l[ni >> 1][(ni & 1)*2];
                    mma_bf16(acc[mi][ni], af_h[mi], b2h);
                    mma_bf16(acc[mi][ni], af_l[mi], b2h);
                    mma_bf16(acc[mi][ni], af_h[mi], b2l);
                }
        }

        if (t + 1 < 32) {
            storeT(1 - cur);
            __syncthreads();
        }
    }

    const float scl = (z == 0) ? QSCALE : 1.f;   // fold softmax scale into Q
    #pragma unroll
    for (int mi = 0; mi < 2; mi++) {
        #pragma unroll
        for (int ni = 0; ni < 4; ni++) {
            int r0 = bm + wm + mi*16 + (lane >> 2);
            int c0 = bn + wn + ni*8 + 2*(lane & 3);
            float bz0 = bias[c0], bz1 = bias[c0 + 1];
            float v0 = acc[mi][ni][0] + bz0;
            float v1 = acc[mi][ni][1] + bz1;
            float v2 = acc[mi][ni][2] + bz0;
            float v3 = acc[mi][ni][3] + bz1;
            if (Cf) {
                float gA = gate[r0], gB = gate[r0 + 8];
                Cf[(size_t)r0*DM + c0]         = v0*gA;
                Cf[(size_t)r0*DM + c0 + 1]     = v1*gA;
                Cf[(size_t)(r0+8)*DM + c0]     = v2*gB;
                Cf[(size_t)(r0+8)*DM + c0 + 1] = v3*gB;
            } else {
                v0 *= scl; v1 *= scl; v2 *= scl; v3 *= scl;
                float h0 = hi_bf16(v0), h1 = hi_bf16(v1);
                float h2 = hi_bf16(v2), h3 = hi_bf16(v3);
                *(uint32_t*)&Ch[(size_t)r0*DM + c0]     = packb(h0, h1);
                *(uint32_t*)&Ch[(size_t)(r0+8)*DM + c0] = packb(h2, h3);
                *(uint32_t*)&Cl[(size_t)r0*DM + c0]     = packb(v0 - h0, v1 - h1);
                *(uint32_t*)&Cl[(size_t)(r0+8)*DM + c0] = packb(v2 - h2, v3 - h3);
            }
        }
    }
}

// ---------------- flash attention: pre-split Q/K/V, zero split ALU in loop ---
// Q carries 0.125*log2e scale; softmax operates directly in base-2 domain.
#define KST 72
#define KVBUF (4*64*KST)       /* elems per buffer = 18432 (36,864 B) */
#define ATTN_SMEM (2*KVBUF*2)  /* bytes = 73,728 */
__global__ __launch_bounds__(256, 1) void attn_bf16(
    const bf16* __restrict__ Qh_g, const bf16* __restrict__ Ql_g,
    const bf16* __restrict__ Kh_g, const bf16* __restrict__ Kl_g,
    const bf16* __restrict__ Vh_g, const bf16* __restrict__ Vl_g,
    float* __restrict__ O)
{
    extern __shared__ __align__(16) bf16 asm_[];
    bf16* Qh = asm_;                 // 128*KST (aliases KV buffer 0)
    bf16* Ql = asm_ + 128*KST;

    const int tid = threadIdx.x, lane = tid & 31, warp = tid >> 5;
    const int qt = blockIdx.x, h = blockIdx.y, b = blockIdx.z;
    const size_t qrow0 = (size_t)(b*SEQ + qt*128);
    const size_t kvrow0 = (size_t)(b*SEQ);
    const int hc = h * HD;

    // stage pre-split Q tile 128x64 (pure copy)
    #pragma unroll
    for (int i = 0; i < 4; i++) {
        int idx = tid + i*256;
        int r = idx >> 3, c8 = (idx & 7) * 8;
        *(uint4*)&Qh[r*KST + c8] = *(const uint4*)(Qh_g + (qrow0 + r)*DM + hc + c8);
        *(uint4*)&Ql[r*KST + c8] = *(const uint4*)(Ql_g + (qrow0 + r)*DM + hc + c8);
    }
    __syncthreads();

    uint32_t qh[4][4], ql[4][4];
    {
        const uint32_t qh_b = smem_u32(Qh), ql_b = smem_u32(Ql);
        #pragma unroll
        for (int kc = 0; kc < 4; kc++) {
            uint32_t off = ((warp*16 + (lane & 15))*KST + kc*16 + (lane >> 4)*8) * 2;
            ldmx4(qh[kc], qh_b + off);
            ldmx4(ql[kc], ql_b + off);
        }
    }
    __syncthreads();   // Q frags in regs; buffer 0 may now be overwritten

    float o[8][4] = {};
    float mrow[2] = {-1e30f, -1e30f};
    float lrow[2] = {0.f, 0.f};

    uint4 pkh[2], pkl[2], pvh[2], pvl[2];
    auto loadKV = [&](int t) {
        #pragma unroll
        for (int i = 0; i < 2; i++) {
            int idx = tid + i*256;
            int r = idx >> 3, c8 = (idx & 7) * 8;
            const size_t g = (kvrow0 + t*64 + r)*DM + hc + c8;
            pkh[i] = *(const uint4*)(Kh_g + g);
            pkl[i] = *(const uint4*)(Kl_g + g);
            pvh[i] = *(const uint4*)(Vh_g + g);
            pvl[i] = *(const uint4*)(Vl_g + g);
        }
    };
    auto storeKV = [&](int buf) {
        bf16* Kh = asm_ + buf*KVBUF;
        bf16* Kl = Kh + 64*KST;
        bf16* Vh = Kl + 64*KST;
        bf16* Vl = Vh + 64*KST;
        #pragma unroll
        for (int i = 0; i < 2; i++) {
            int idx = tid + i*256;
            int r = idx >> 3, c8 = (idx & 7) * 8;
            *(uint4*)&Kh[r*KST + c8] = pkh[i];
            *(uint4*)&Kl[r*KST + c8] = pkl[i];
            *(uint4*)&Vh[r*KST + c8] = pvh[i];
            *(uint4*)&Vl[r*KST + c8] = pvl[i];
        }
    };

    loadKV(0); storeKV(0); __syncthreads();

    for (int t = 0; t < SEQ/64; t++) {
        const int cur = t & 1;
        if (t + 1 < SEQ/64) loadKV(t + 1);

        const uint32_t base = smem_u32(asm_ + cur*KVBUF);
        const uint32_t kh_b = base;
        const uint32_t kl_b = base + 64*KST*2;
        const uint32_t vh_b = base + 64*KST*4;
        const uint32_t vl_b = base + 64*KST*6;

        // ---- S = Q K^T (3xBF16); Q pre-scaled by 0.125*log2e ----
        float s[8][4] = {};
        #pragma unroll
        for (int kc = 0; kc < 4; kc++) {
            #pragma unroll
            for (int nip = 0; nip < 4; nip++) {
                uint32_t off = ((nip*16 + (lane >> 4)*8 + (lane & 7))*KST
                                + kc*16 + ((lane >> 3) & 1)*8) * 2;
                uint32_t kf_h[4], kf_l[4];
                ldmx4(kf_h, kh_b + off);
                ldmx4(kf_l, kl_b + off);
                #pragma unroll
                for (int hf = 0; hf < 2; hf++) {
                    int ni = nip*2 + hf;
                    mma_bf16(s[ni], qh[kc], &kf_h[hf*2]);
                    mma_bf16(s[ni], ql[kc], &kf_h[hf*2]);
                    mma_bf16(s[ni], qh[kc], &kf_l[hf*2]);
                }
            }
        }

        // ---- online softmax per row-half (base-2 domain; s already scaled) --
        #pragma unroll
        for (int rh = 0; rh < 2; rh++) {
            float mx = -1e30f;
            #pragma unroll
            for (int ni = 0; ni < 8; ni++)
                mx = fmaxf(mx, fmaxf(s[ni][rh*2], s[ni][rh*2+1]));
            mx = fmaxf(mx, __shfl_xor_sync(0xffffffffu, mx, 1));
            mx = fmaxf(mx, __shfl_xor_sync(0xffffffffu, mx, 2));
            float mnew  = fmaxf(mrow[rh], mx);
            float alpha = exp2f(mrow[rh] - mnew);
            mrow[rh] = mnew;
            float sum = 0.f;
            #pragma unroll
            for (int ni = 0; ni < 8; ni++) {
                s[ni][rh*2]   = exp2f(s[ni][rh*2]   - mnew);
                s[ni][rh*2+1] = exp2f(s[ni][rh*2+1] - mnew);
                sum += s[ni][rh*2] + s[ni][rh*2+1];
            }
            sum += __shfl_xor_sync(0xffffffffu, sum, 1);
            sum += __shfl_xor_sync(0xffffffffu, sum, 2);
            lrow[rh] = lrow[rh]*alpha + sum;
            #pragma unroll
            for (int ni = 0; ni < 8; ni++) { o[ni][rh*2] *= alpha; o[ni][rh*2+1] *= alpha; }
        }

        // ---- O += P V (3xBF16); P fragments built directly from s regs ----
        #pragma unroll
        for (int kcp = 0; kcp < 4; kcp++) {
            uint32_t pa_h[4], pa_l[4];
            #pragma unroll
            for (int j = 0; j < 2; j++) {
                float e0 = s[2*kcp + j][0], e1 = s[2*kcp + j][1];
                float e2 = s[2*kcp + j][2], e3 = s[2*kcp + j][3];
                float h0 = hi_bf16(e0), h1 = hi_bf16(e1), h2 = hi_bf16(e2), h3 = hi_bf16(e3);
                pa_h[2*j]   = packb(h0, h1);
                pa_h[2*j+1] = packb(h2, h3);
                pa_l[2*j]   = packb(e0 - h0, e1 - h1);
                pa_l[2*j+1] = packb(e2 - h2, e3 - h3);
            }
            #pragma unroll
            for (int nip = 0; nip < 4; nip++) {
                uint32_t off = ((kcp*16 + ((lane >> 3) & 1)*8 + (lane & 7))*KST
                                + nip*16 + (lane >> 4)*8) * 2;
                uint32_t vf_h[4], vf_l[4];
                ldmx4t(vf_h, vh_b + off);
                ldmx4t(vf_l, vl_b + off);
                #pragma unroll
                for (int hf = 0; hf < 2; hf++) {
                    int ni = nip*2 + hf;
                    mma_bf16(o[ni], pa_h, &vf_h[hf*2]);
                    mma_bf16(o[ni], pa_l, &vf_h[hf*2]);
                    mma_bf16(o[ni], pa_h, &vf_l[hf*2]);
                }
            }
        }

        if (t + 1 < SEQ/64) {
            storeKV(1 - cur);
            __syncthreads();
        }
    }

    float inv0 = 1.f / lrow[0], inv1 = 1.f / lrow[1];
    int r = warp*16 + (lane >> 2);
    float* obase = O + ((qrow0)*DM + hc);
    #pragma unroll
    for (int ni = 0; ni < 8; ni++) {
        int c = ni*8 + 2*(lane & 3);
        obase[(size_t)r*DM + c]         = o[ni][0]*inv0;
        obase[(size_t)r*DM + c + 1]     = o[ni][1]*inv0;
        obase[(size_t)(r+8)*DM + c]     = o[ni][2]*inv1;
        obase[(size_t)(r+8)*DM + c + 1] = o[ni][3]*inv1;
    }
}

// ---------------- final LN ---------------------------------------------------
__global__ __launch_bounds__(256) void ln_out_kernel(
    const float* __restrict__ x, const float* __restrict__ gg,
    const float* __restrict__ bb, float* __restrict__ out)
{
    const int row = blockIdx.x;
    const int tid = threadIdx.x, lane = tid & 31, warp = tid >> 5;
    float4 xv = ((const float4*)(x + (size_t)row*DM))[tid];
    float s  = xv.x + xv.y + xv.z + xv.w;
    float ss = xv.x*xv.x + xv.y*xv.y + xv.z*xv.z + xv.w*xv.w;
    __shared__ __align__(16) float red[16];
    #pragma unroll
    for (int off = 16; off; off >>= 1) {
        s  += __shfl_xor_sync(0xffffffffu, s,  off);
        ss += __shfl_xor_sync(0xffffffffu, ss, off);
    }
    if (lane == 0) { red[warp] = s; red[8 + warp] = ss; }
    __syncthreads();
    float st = 0.f, sst = 0.f;
    #pragma unroll
    for (int i = 0; i < 8; i++) { st += red[i]; sst += red[8 + i]; }
    float mu   = st * (1.f/DM);
    float var  = sst * (1.f/DM) - mu*mu;
    float rstd = rsqrtf(var + EPS);
    float4 gv = ((const float4*)gg)[tid];
    float4 bv = ((const float4*)bb)[tid];
    float4 yv;
    yv.x = (xv.x - mu)*rstd*gv.x + bv.x;
    yv.y = (xv.y - mu)*rstd*gv.y + bv.y;
    yv.z = (xv.z - mu)*rstd*gv.z + bv.z;
    yv.w = (xv.w - mu)*rstd*gv.w + bv.w;
    ((float4*)(out + (size_t)row*DM))[tid] = yv;
}

// ---------------- launch -----------------------------------------------------
extern "C" void kernel_launch(void* const* d_in, const int* in_sizes, int n_in,
                              void* d_out, int out_size) {
    const float* query  = (const float*)d_in[0];
    const float* key_   = (const float*)d_in[1];
    const float* value  = (const float*)d_in[2];
    const float* Wq     = (const float*)d_in[3];
    const float* bq     = (const float*)d_in[4];
    const float* Wk     = (const float*)d_in[5];
    const float* bk     = (const float*)d_in[6];
    const float* Wv     = (const float*)d_in[7];
    const float* bv     = (const float*)d_in[8];
    const float* Wo     = (const float*)d_in[9];
    const float* bo     = (const float*)d_in[10];
    const float* Wg     = (const float*)d_in[11];
    const float* ln_q_g = (const float*)d_in[12];
    const float* ln_q_b = (const float*)d_in[13];
    const float* ln_kv_g= (const float*)d_in[14];
    const float* ln_kv_b= (const float*)d_in[15];
    const float* ln_o_g = (const float*)d_in[16];
    const float* ln_o_b = (const float*)d_in[17];

    float *qn, *kn, *vn, *ao, *y, *gate;
    bf16 *wh, *wl, *qph, *qpl, *kph, *kpl, *vph, *vpl;
    cudaGetSymbolAddress((void**)&qn,  g_qn);
    cudaGetSymbolAddress((void**)&kn,  g_kn);
    cudaGetSymbolAddress((void**)&vn,  g_vn);
    cudaGetSymbolAddress((void**)&ao,  g_ao);
    cudaGetSymbolAddress((void**)&y,   g_y);
    cudaGetSymbolAddress((void**)&gate,g_gate);
    cudaGetSymbolAddress((void**)&wh,  g_wh);
    cudaGetSymbolAddress((void**)&wl,  g_wl);
    cudaGetSymbolAddress((void**)&qph, g_qph); cudaGetSymbolAddress((void**)&qpl, g_qpl);
    cudaGetSymbolAddress((void**)&kph, g_kph); cudaGetSymbolAddress((void**)&kpl, g_kpl);
    cudaGetSymbolAddress((void**)&vph, g_vph); cudaGetSymbolAddress((void**)&vpl, g_vpl);

    bf16* whm[4] = {wh, wh + (size_t)DM*DM, wh + 2*(size_t)DM*DM, wh + 3*(size_t)DM*DM};
    bf16* wlm[4] = {wl, wl + (size_t)DM*DM, wl + 2*(size_t)DM*DM, wl + 3*(size_t)DM*DM};

    cudaFuncSetAttribute(gemm_bf16x3, cudaFuncAttributeMaxDynamicSharedMemorySize, GEMM_SMEM);
    cudaFuncSetAttribute(attn_bf16,  cudaFuncAttributeMaxDynamicSharedMemorySize, ATTN_SMEM);

    splitw_kernel<<<dim3(1024, 4), 256>>>(Wq, Wk, Wv, Wo,
        whm[0], wlm[0], whm[1], wlm[1], whm[2], wlm[2], whm[3], wlm[3]);
    ln3_kernel<<<dim3(MTOT, 3), 256>>>(query, key_, value,
                                       ln_q_g, ln_q_b, ln_kv_g, ln_kv_b,
                                       Wg, qn, kn, vn, gate);
    // merged QKV projections -> packed bf16 hi/lo outputs (Q pre-scaled)
    gemm_bf16x3<<<dim3(16, 64, 3), 256, GEMM_SMEM>>>(qn, kn, vn, wh, wl, 0,
                                          bq, bk, bv, nullptr, nullptr,
                                          qph, qpl, kph, kpl, vph, vpl);
    attn_bf16<<<dim3(SEQ/128, NH, BATCH), 256, ATTN_SMEM>>>(qph, qpl, kph, kpl, vph, vpl, ao);
    // output projection with gate epilogue (fp32 out)
    gemm_bf16x3<<<dim3(16, 64, 1), 256, GEMM_SMEM>>>(ao, ao, ao, wh, wl, 3,
                                          bo, bo, bo, gate, y,
                                          nullptr, nullptr, nullptr, nullptr, nullptr, nullptr);
    ln_out_kernel<<<MTOT, 256>>>(y, ln_o_g, ln_o_b, (float*)d_out);
}